// round 2
// baseline (speedup 1.0000x reference)
#include <cuda_runtime.h>

#define HH   1024
#define NST  64
#define LL   2048
#define LANES 32
#define MSTEPS 32   // packed steps: 32 x (even,odd) pairs = 64 l-values per lane

typedef unsigned long long ull;

// Scratch: per (h,n): [cmr, cmi, ar, ai] and [w32r, w32i, q32, P64]
__device__ float4 g_par[HH * NST * 2];

// ---- packed f32x2 helpers (sm_100+ PTX; ptxas never auto-generates these) ----
__device__ __forceinline__ ull pk2(float lo, float hi) {
    ull r; asm("mov.b64 %0, {%1, %2};" : "=l"(r) : "f"(lo), "f"(hi)); return r;
}
__device__ __forceinline__ void unpk2(ull v, float* lo, float* hi) {
    asm("mov.b64 {%0, %1}, %2;" : "=f"(*lo), "=f"(*hi) : "l"(v));
}
__device__ __forceinline__ ull fma2(ull a, ull b, ull c) {
    ull d; asm("fma.rn.f32x2 %0, %1, %2, %3;" : "=l"(d) : "l"(a), "l"(b), "l"(c)); return d;
}
__device__ __forceinline__ ull mul2(ull a, ull b) {
    ull d; asm("mul.rn.f32x2 %0, %1, %2;" : "=l"(d) : "l"(a), "l"(b)); return d;
}
__device__ __forceinline__ ull add2(ull a, ull b) {
    ull d; asm("add.rn.f32x2 %0, %1, %2;" : "=l"(d) : "l"(a), "l"(b)); return d;
}

// Accurate sincos for |x| <= ~110, independent of compiler fast-math flags.
__device__ __forceinline__ void my_sincos(float x, float* sp, float* cp) {
    float k = rintf(x * 0.63661977236f);           // x * 2/pi
    float r = fmaf(k, -1.57079637e+0f, x);         // x - k*PIO2_HI
    r = fmaf(k, 4.37113900e-8f, r);                // + k*PIO2_MID
    int q = ((int)k) & 3;
    float r2 = r * r;
    float s0 = fmaf(r2, -1.9515296e-4f, 8.3321609e-3f);
    s0 = fmaf(r2, s0, -1.6666655e-1f);
    float sr = fmaf(r * r2, s0, r);
    float c0 = fmaf(r2, 2.4433157e-5f, -1.3887316e-3f);
    c0 = fmaf(r2, c0, 4.1666646e-2f);
    c0 = fmaf(r2, c0, -0.5f);
    float cr = fmaf(r2, c0, 1.0f);
    float ss = (q & 1) ? cr : sr;
    float cc = (q & 1) ? sr : cr;
    if (q == 1 || q == 2) cc = -cc;
    if (q >= 2) ss = -ss;
    *sp = ss; *cp = cc;
}

// Kernel 1: parameter preprocessing. One thread per (h, n).
__global__ void s4d_prep(const float* __restrict__ A_real,
                         const float* __restrict__ A_imag,
                         const float* __restrict__ B,
                         const float* __restrict__ C,
                         const float* __restrict__ inv_dt) {
    int i = blockIdx.x * blockDim.x + threadIdx.x;
    if (i >= HH * NST) return;
    int h = i / NST;

    float dt  = __expf(inv_dt[h]);
    float Are = -__expf(A_real[i]);
    float Aim = A_imag[i];
    float ar  = Are * dt;
    float ai  = Aim * dt;

    // exp(dtA) - 1
    float ea = __expf(ar);
    float sa, ca; my_sincos(ai, &sa, &ca);
    float er = fmaf(ea, ca, -1.0f);
    float ei = ea * sa;

    // (exp(dtA)-1) / A
    float inv = 1.0f / fmaf(Are, Are, Aim * Aim);
    float fr = (er * Are + ei * Aim) * inv;
    float fi = (ei * Are - er * Aim) * inv;

    // Cm = B * C * f, fold in the global factor 2
    float br  = B[2 * i], bi  = B[2 * i + 1];
    float c0r = C[2 * i], c0i = C[2 * i + 1];
    float bcr = br * c0r - bi * c0i;
    float bci = br * c0i + bi * c0r;
    float cmr = 2.0f * (bcr * fr - bci * fi);
    float cmi = 2.0f * (bcr * fi + bci * fr);

    // W32 = exp(32*dtA), Q32 = |W32|^2 = exp(64*ar), P64 = 2*Re(W32^2)
    float e32 = __expf(32.0f * ar);
    float s32, c32; my_sincos(32.0f * ai, &s32, &c32);
    float w32r = e32 * c32;
    float w32i = e32 * s32;
    float q32  = e32 * e32;
    float P64  = 2.0f * (w32r * w32r - w32i * w32i);

    g_par[2 * i]     = make_float4(cmr, cmi, ar, ai);
    g_par[2 * i + 1] = make_float4(w32r, w32i, q32, P64);
}

// Kernel 2: packed-recurrence Vandermonde contraction.
// One warp per h; lane t owns l = t + 32k, k = 0..63.
// v_k = Re(Cm * w^(t+32k)). Even/odd subsequences (stride 64) packed into one
// f32x2: u_m = (v_{2m}, v_{2m+1}),  u_m = P64 (x) u_{m-1} - Q64 (x) u_{m-2}.
// 3 packed fma-pipe instrs per 2 output elements.
__global__ void __launch_bounds__(LANES) s4d_main(float* __restrict__ out) {
    int h = blockIdx.x;
    int t = threadIdx.x;
    float tf = (float)t;

    ull acc[MSTEPS];
#pragma unroll
    for (int m = 0; m < MSTEPS; m++) acc[m] = 0ULL;

    const float4* par = &g_par[h * NST * 2];

    for (int n = 0; n < NST; n++) {
        float4 p0 = __ldg(&par[2 * n]);
        float4 p1 = __ldg(&par[2 * n + 1]);
        float cmr = p0.x, cmi = p0.y, ar = p0.z, ai = p0.w;
        float w32r = p1.x, w32i = p1.y, q32 = p1.z, P64 = p1.w;

        // z = Cm * w^t
        float e = __expf(ar * tf);
        float s, c; my_sincos(ai * tf, &s, &c);
        float zr = e * (cmr * c - cmi * s);
        float zi = e * (cmr * s + cmi * c);

        // Seed values via the stride-32 scalar recurrence
        float v0 = zr;                                   // Re(Cm w^t)
        float v1 = fmaf(zr, w32r, -(zi * w32i));         // Re(Cm w^(t+32))
        float P32 = w32r + w32r;
        float v2 = fmaf(P32, v1, -(q32 * v0));
        float v3 = fmaf(P32, v2, -(q32 * v1));

        ull u0 = pk2(v0, v1);
        ull u1 = pk2(v2, v3);
        float Qn = -(q32 * q32);                         // -Q64 = -exp(128*ar)
        ull Pp = pk2(P64, P64);
        ull Qp = pk2(Qn, Qn);

        acc[0] = add2(acc[0], u0);
        acc[1] = add2(acc[1], u1);
#pragma unroll
        for (int m = 2; m < MSTEPS; m++) {
            ull mm = mul2(Qp, u0);          // -Q64 * u_{m-2}
            ull un = fma2(Pp, u1, mm);      // P64 * u_{m-1} - Q64 * u_{m-2}
            acc[m] = add2(acc[m], un);
            u0 = u1;
            u1 = un;
        }
    }

    // acc[m] = (v at l = t+64m, v at l = t+64m+32) : coalesced stores
    float* o = out + h * LL + t;
#pragma unroll
    for (int m = 0; m < MSTEPS; m++) {
        float lo, hi; unpk2(acc[m], &lo, &hi);
        o[64 * m]      = lo;
        o[64 * m + 32] = hi;
    }
}

extern "C" void kernel_launch(void* const* d_in, const int* in_sizes, int n_in,
                              void* d_out, int out_size) {
    const float* A_real = (const float*)d_in[0];
    const float* A_imag = (const float*)d_in[1];
    const float* B      = (const float*)d_in[2];
    const float* C      = (const float*)d_in[3];
    const float* inv_dt = (const float*)d_in[4];
    float* out = (float*)d_out;

    s4d_prep<<<(HH * NST + 255) / 256, 256>>>(A_real, A_imag, B, C, inv_dt);
    s4d_main<<<HH, LANES>>>(out);
}

// round 3
// speedup vs baseline: 1.6655x; 1.6655x over previous
#include <cuda_runtime.h>

#define HH    1024
#define NST   64
#define LL    2048
#define NWARP 4
#define NPW   (NST / NWARP)   // 16 n-values per warp
#define CHUNK 64              // l-values per lane (LL / 32)

// Scratch: per (h,n): [cmr, cmi, ar, ai] and [w32r, w32i, q32, pad]
__device__ float4 g_par[HH * NST * 2];

// Accurate sincos for |x| <= ~110, independent of compiler fast-math flags.
__device__ __forceinline__ void my_sincos(float x, float* sp, float* cp) {
    float k = rintf(x * 0.63661977236f);           // x * 2/pi
    float r = fmaf(k, -1.57079637e+0f, x);         // x - k*PIO2_HI
    r = fmaf(k, 4.37113900e-8f, r);                // + k*PIO2_MID
    int q = ((int)k) & 3;
    float r2 = r * r;
    float s0 = fmaf(r2, -1.9515296e-4f, 8.3321609e-3f);
    s0 = fmaf(r2, s0, -1.6666655e-1f);
    float sr = fmaf(r * r2, s0, r);
    float c0 = fmaf(r2, 2.4433157e-5f, -1.3887316e-3f);
    c0 = fmaf(r2, c0, 4.1666646e-2f);
    c0 = fmaf(r2, c0, -0.5f);
    float cr = fmaf(r2, c0, 1.0f);
    float ss = (q & 1) ? cr : sr;
    float cc = (q & 1) ? sr : cr;
    if (q == 1 || q == 2) cc = -cc;
    if (q >= 2) ss = -ss;
    *sp = ss; *cp = cc;
}

// Kernel 1: parameter preprocessing. One thread per (h, n).
__global__ void s4d_prep(const float* __restrict__ A_real,
                         const float* __restrict__ A_imag,
                         const float* __restrict__ B,
                         const float* __restrict__ C,
                         const float* __restrict__ inv_dt) {
    int i = blockIdx.x * blockDim.x + threadIdx.x;
    if (i >= HH * NST) return;
    int h = i / NST;

    float dt  = __expf(inv_dt[h]);
    float Are = -__expf(A_real[i]);
    float Aim = A_imag[i];
    float ar  = Are * dt;
    float ai  = Aim * dt;

    // exp(dtA) - 1
    float ea = __expf(ar);
    float sa, ca; my_sincos(ai, &sa, &ca);
    float er = fmaf(ea, ca, -1.0f);
    float ei = ea * sa;

    // (exp(dtA)-1) / A
    float inv = 1.0f / fmaf(Are, Are, Aim * Aim);
    float fr = (er * Are + ei * Aim) * inv;
    float fi = (ei * Are - er * Aim) * inv;

    // Cm = B * C * f, fold in the global factor 2
    float br  = B[2 * i], bi  = B[2 * i + 1];
    float c0r = C[2 * i], c0i = C[2 * i + 1];
    float bcr = br * c0r - bi * c0i;
    float bci = br * c0i + bi * c0r;
    float cmr = 2.0f * (bcr * fr - bci * fi);
    float cmi = 2.0f * (bcr * fi + bci * fr);

    // W32 = exp(32*dtA), q32 = |W32|^2 = exp(64*ar)
    float e32 = __expf(32.0f * ar);
    float s32, c32; my_sincos(32.0f * ai, &s32, &c32);
    float w32r = e32 * c32;
    float w32i = e32 * s32;
    float q32  = e32 * e32;

    g_par[2 * i]     = make_float4(cmr, cmi, ar, ai);
    g_par[2 * i + 1] = make_float4(w32r, w32i, q32, 0.0f);
}

// Kernel 2: 4 warps per h; warp w handles n in [16w, 16w+16) over the full
// l-range. Lane t owns l = t + 32k, k = 0..63, via the order-2 recurrence
// x_k = p*x_{k-1} - q*x_{k-2}, p = 2*Re(w^32), q = |w^32|^2.
// Partial sums reduced across the 4 warps through shared memory.
__global__ void __launch_bounds__(32 * NWARP) s4d_main(float* __restrict__ out) {
    __shared__ float red[NWARP][CHUNK][32];

    int h   = blockIdx.x;
    int tid = threadIdx.x;
    int w   = tid >> 5;
    int t   = tid & 31;
    float tf = (float)t;

    float acc[CHUNK];
#pragma unroll
    for (int j = 0; j < CHUNK; j++) acc[j] = 0.0f;

    const float4* par = &g_par[(h * NST + w * NPW) * 2];

    for (int n = 0; n < NPW; n++) {
        float4 p0 = __ldg(&par[2 * n]);
        float4 p1 = __ldg(&par[2 * n + 1]);
        float cmr = p0.x, cmi = p0.y, ar = p0.z, ai = p0.w;
        float w32r = p1.x, w32i = p1.y, q = p1.z;

        // z = Cm * w^t
        float e = __expf(ar * tf);
        float s, c; my_sincos(ai * tf, &s, &c);
        float zr = e * (cmr * c - cmi * s);
        float zi = e * (cmr * s + cmi * c);

        float x2 = zr;                              // Re(Cm w^t)
        float x1 = fmaf(zr, w32r, -(zi * w32i));    // Re(Cm w^(t+32))
        float p  = w32r + w32r;

        acc[0] += x2;
        acc[1] += x1;
#pragma unroll
        for (int j = 2; j < CHUNK; j++) {
            float m = q * x2;
            float x = fmaf(p, x1, -m);
            acc[j] += x;
            x2 = x1;
            x1 = x;
        }
    }

    // Stage partial sums: red[w][j][t]
#pragma unroll
    for (int j = 0; j < CHUNK; j++) red[w][j][t] = acc[j];
    __syncthreads();

    // Reduce across warps and store. Element e = 32*j + t maps to out[h, e];
    // consecutive tid -> consecutive e -> coalesced, conflict-free LDS.
    float* o = out + h * LL;
    for (int e = tid; e < LL; e += 32 * NWARP) {
        int j  = e >> 5;
        int tt = e & 31;
        float s = red[0][j][tt] + red[1][j][tt] + red[2][j][tt] + red[3][j][tt];
        o[e] = s;
    }
}

extern "C" void kernel_launch(void* const* d_in, const int* in_sizes, int n_in,
                              void* d_out, int out_size) {
    const float* A_real = (const float*)d_in[0];
    const float* A_imag = (const float*)d_in[1];
    const float* B      = (const float*)d_in[2];
    const float* C      = (const float*)d_in[3];
    const float* inv_dt = (const float*)d_in[4];
    float* out = (float*)d_out;

    s4d_prep<<<(HH * NST + 255) / 256, 256>>>(A_real, A_imag, B, C, inv_dt);
    s4d_main<<<HH, 32 * NWARP>>>(out);
}

// round 4
// speedup vs baseline: 1.8351x; 1.1018x over previous
#include <cuda_runtime.h>

#define HH    1024
#define NST   64
#define LL    2048
#define NWARP 4
#define NPW   (NST / NWARP)   // 16 n per warp

// Per (h,n) parameters:
// g_pA = (cmr, cmi, cm1024r, cm1024i)   Cm has the global 2x folded in
// g_pB = (wr, wi, w32r, w32i)
// g_pC = (w64r, w64i)
__device__ float4 g_pA[HH * NST];
__device__ float4 g_pB[HH * NST];
__device__ float2 g_pC[HH * NST];

// Accurate sincos for |x| <= ~110, independent of compiler fast-math flags.
__device__ __forceinline__ void my_sincos(float x, float* sp, float* cp) {
    float k = rintf(x * 0.63661977236f);           // x * 2/pi
    float r = fmaf(k, -1.57079637e+0f, x);         // x - k*PIO2_HI
    r = fmaf(k, 4.37113900e-8f, r);                // + k*PIO2_MID
    int q = ((int)k) & 3;
    float r2 = r * r;
    float s0 = fmaf(r2, -1.9515296e-4f, 8.3321609e-3f);
    s0 = fmaf(r2, s0, -1.6666655e-1f);
    float sr = fmaf(r * r2, s0, r);
    float c0 = fmaf(r2, 2.4433157e-5f, -1.3887316e-3f);
    c0 = fmaf(r2, c0, 4.1666646e-2f);
    c0 = fmaf(r2, c0, -0.5f);
    float cr = fmaf(r2, c0, 1.0f);
    float ss = (q & 1) ? cr : sr;
    float cc = (q & 1) ? sr : cr;
    if (q == 1 || q == 2) cc = -cc;
    if (q >= 2) ss = -ss;
    *sp = ss; *cp = cc;
}

// Kernel 1: parameter preprocessing. One thread per (h, n).
__global__ void s4d_prep(const float* __restrict__ A_real,
                         const float* __restrict__ A_imag,
                         const float* __restrict__ B,
                         const float* __restrict__ C,
                         const float* __restrict__ inv_dt) {
    int i = blockIdx.x * blockDim.x + threadIdx.x;
    if (i >= HH * NST) return;
    int h = i / NST;

    float dt  = __expf(inv_dt[h]);
    float Are = -__expf(A_real[i]);
    float Aim = A_imag[i];
    float ar  = Are * dt;     // always < 0
    float ai  = Aim * dt;

    // w = exp(dtA);  exp(dtA) - 1
    float ea = __expf(ar);
    float sa, ca; my_sincos(ai, &sa, &ca);
    float wr = ea * ca;
    float wi = ea * sa;
    float er = wr - 1.0f;
    float ei = wi;

    // (exp(dtA)-1) / A
    float inv = 1.0f / fmaf(Are, Are, Aim * Aim);
    float fr = (er * Are + ei * Aim) * inv;
    float fi = (ei * Are - er * Aim) * inv;

    // Cm = B * C * f, fold in the global factor 2
    float br  = B[2 * i], bi  = B[2 * i + 1];
    float c0r = C[2 * i], c0i = C[2 * i + 1];
    float bcr = br * c0r - bi * c0i;
    float bci = br * c0i + bi * c0r;
    float cmr = 2.0f * (bcr * fr - bci * fi);
    float cmi = 2.0f * (bcr * fi + bci * fr);

    // w32 = exp(32*dtA)
    float e32 = __expf(32.0f * ar);
    float s32, c32; my_sincos(32.0f * ai, &s32, &c32);
    float w32r = e32 * c32;
    float w32i = e32 * s32;

    // w64 = w32^2 ; w1024 = w64^16 via 4 squarings (|w|<1: may underflow to 0, fine)
    float w64r = fmaf(w32r, w32r, -(w32i * w32i));
    float w64i = 2.0f * w32r * w32i;
    float xr = w64r, xi = w64i;
#pragma unroll
    for (int s = 0; s < 4; s++) {
        float nr = fmaf(xr, xr, -(xi * xi));
        float ni = 2.0f * xr * xi;
        xr = nr; xi = ni;
    }
    float cm1024r = fmaf(cmr, xr, -(cmi * xi));
    float cm1024i = fmaf(cmr, xi,  cmi * xr);

    g_pA[i] = make_float4(cmr, cmi, cm1024r, cm1024i);
    g_pB[i] = make_float4(wr, wi, w32r, w32i);
    g_pC[i] = make_float2(w64r, w64i);
}

// Kernel 2: chirp-factorized contraction.
// l = j1 + 64*j2 (j1<64, j2<32):
//   K[h,l] = sum_n Re( W2[n,j2] * W1[n,j1] ),
//   W1[n,j1] = w_n^j1,  W2[n,j2] = Cm_n * (w_n^64)^j2.
// Lane t holds acc for j1 = t and j1 = t+32, all 32 j2 -> 64 regs.
// Warp w covers n in [16w, 16w+16). Inner op = 2 FFMA per (n, l).
__global__ void __launch_bounds__(32 * NWARP) s4d_main(float* __restrict__ out) {
    __shared__ __align__(16) char sraw[49152];
    float2* W1sh = (float2*)sraw;             // [64 n][64 j1], j1-low5 XOR (n&31)
    float2* W2sh = (float2*)(sraw + 32768);   // [32 j2][64 n]
    float*  red  = (float*)sraw;              // overlay after main loop (32KB)

    int h   = blockIdx.x;
    int tid = threadIdx.x;
    int w   = tid >> 5;
    int t   = tid & 31;

    // ---- Table generation: thread -> (n = tid/2, hh = tid&1) ----
    {
        int n  = tid >> 1;
        int hh = tid & 1;
        int gi = h * NST + n;
        int swz = n & 31;

        float4 pB = g_pB[gi];
        // W1 chain: seed w^(32*hh), step w; store swizzled.
        float cr = hh ? pB.z : 1.0f;
        float ci = hh ? pB.w : 0.0f;
        float2* w1row = W1sh + n * 64 + hh * 32;
#pragma unroll
        for (int k = 0; k < 32; k++) {
            w1row[k ^ swz] = make_float2(cr, ci);
            float nr = fmaf(cr, pB.x, -(ci * pB.y));
            float ni = fmaf(cr, pB.y,   ci * pB.x);
            cr = nr; ci = ni;
        }

        float4 pA = g_pA[gi];
        float2 pC = g_pC[gi];
        // W2 chain: seed Cm (hh=0) or Cm*w^1024 (hh=1), step w64.
        float sr = hh ? pA.z : pA.x;
        float si = hh ? pA.w : pA.y;
#pragma unroll
        for (int k = 0; k < 16; k++) {
            W2sh[(hh * 16 + k) * 64 + n] = make_float2(sr, si);
            float nr = fmaf(sr, pC.x, -(si * pC.y));
            float ni = fmaf(sr, pC.y,   si * pC.x);
            sr = nr; si = ni;
        }
    }
    __syncthreads();

    // ---- Main contraction ----
    float accA[32], accB[32];
#pragma unroll
    for (int j = 0; j < 32; j++) { accA[j] = 0.0f; accB[j] = 0.0f; }

    for (int n = w * NPW; n < w * NPW + NPW; n++) {
        int swz = n & 31;
        float2 w1a = W1sh[n * 64 + (t ^ swz)];        // w^t
        float2 w1b = W1sh[n * 64 + 32 + (t ^ swz)];   // w^(t+32)
        const float2* w2p = W2sh + n;
#pragma unroll
        for (int j = 0; j < 32; j++) {
            float2 w2 = w2p[j * 64];                  // broadcast
            accA[j] = fmaf(w2.x, w1a.x, accA[j]);
            accA[j] = fmaf(-w2.y, w1a.y, accA[j]);
            accB[j] = fmaf(w2.x, w1b.x, accB[j]);
            accB[j] = fmaf(-w2.y, w1b.y, accB[j]);
        }
    }
    __syncthreads();   // all W1/W2 reads done before overlay

    // ---- Stage partials: red[w][a][t], a = half*32 + j2 ----
#pragma unroll
    for (int j = 0; j < 32; j++) {
        red[(w * 64 + j) * 32 + t]      = accA[j];
        red[(w * 64 + 32 + j) * 32 + t] = accB[j];
    }
    __syncthreads();

    // ---- Reduce 4 warps, store coalesced ----
    float* o = out + h * LL;
    for (int e = tid; e < LL; e += 32 * NWARP) {
        int j2 = e >> 6;
        int j1 = e & 63;
        int a  = ((j1 >> 5) << 5) + j2;   // half*32 + j2
        int tt = j1 & 31;
        float s = red[(0 * 64 + a) * 32 + tt] + red[(1 * 64 + a) * 32 + tt]
                + red[(2 * 64 + a) * 32 + tt] + red[(3 * 64 + a) * 32 + tt];
        o[e] = s;
    }
}

extern "C" void kernel_launch(void* const* d_in, const int* in_sizes, int n_in,
                              void* d_out, int out_size) {
    const float* A_real = (const float*)d_in[0];
    const float* A_imag = (const float*)d_in[1];
    const float* B      = (const float*)d_in[2];
    const float* C      = (const float*)d_in[3];
    const float* inv_dt = (const float*)d_in[4];
    float* out = (float*)d_out;

    s4d_prep<<<(HH * NST + 255) / 256, 256>>>(A_real, A_imag, B, C, inv_dt);
    s4d_main<<<HH, 32 * NWARP>>>(out);
}

// round 5
// speedup vs baseline: 1.9778x; 1.0778x over previous
#include <cuda_runtime.h>

#define HH    1024
#define NST   64
#define LL    2048
#define NWARP 4
#define NPW   (NST / NWARP)   // 16 n per warp

// Accurate sincos for |x| <= ~110, independent of compiler fast-math flags.
__device__ __forceinline__ void my_sincos(float x, float* sp, float* cp) {
    float k = rintf(x * 0.63661977236f);           // x * 2/pi
    float r = fmaf(k, -1.57079637e+0f, x);         // x - k*PIO2_HI
    r = fmaf(k, 4.37113900e-8f, r);                // + k*PIO2_MID
    int q = ((int)k) & 3;
    float r2 = r * r;
    float s0 = fmaf(r2, -1.9515296e-4f, 8.3321609e-3f);
    s0 = fmaf(r2, s0, -1.6666655e-1f);
    float sr = fmaf(r * r2, s0, r);
    float c0 = fmaf(r2, 2.4433157e-5f, -1.3887316e-3f);
    c0 = fmaf(r2, c0, 4.1666646e-2f);
    c0 = fmaf(r2, c0, -0.5f);
    float cr = fmaf(r2, c0, 1.0f);
    float ss = (q & 1) ? cr : sr;
    float cc = (q & 1) ? sr : cr;
    if (q == 1 || q == 2) cc = -cc;
    if (q >= 2) ss = -ss;
    *sp = ss; *cp = cc;
}

// Single fused kernel. One CTA per h, 4 warps.
// Chirp factorization: l = j1 + 64*j2 (j1<64, j2<32):
//   K[h,l] = sum_n Re( W2[n,j2] * W1[n,j1] ),
//   W1[n,j1] = w_n^j1,  W2[n,j2] = Cm_n * (w_n^64)^j2   (2x folded into Cm).
// W1sh[n][t] = float4(w^t, w^(t+32)), slot t XOR (n&31).
// W2sh[n][p] = float4(W2[2p], W2[2p+1]), slot p XOR (n&15).
// Lane t accumulates j1 = t (accA) and j1 = t+32 (accB) for all 32 j2.
// Inner op: 1 LDS.128 broadcast per 8 FFMA.
__global__ void __launch_bounds__(32 * NWARP, 4) s4d_all(
        const float* __restrict__ A_real,
        const float* __restrict__ A_imag,
        const float* __restrict__ Bg,
        const float* __restrict__ Cg,
        const float* __restrict__ inv_dt,
        float* __restrict__ out) {
    __shared__ __align__(16) char sraw[49152];
    float4* W1sh = (float4*)sraw;             // [64 n][32 t]  = 32KB
    float4* W2sh = (float4*)(sraw + 32768);   // [64 n][16 p]  = 16KB
    float*  red  = (float*)sraw;              // overlay after main loop

    int h   = blockIdx.x;
    int tid = threadIdx.x;
    int w   = tid >> 5;
    int t   = tid & 31;

    // ---------- Param computation (in registers, lanes 2q,2q+1 duplicate n=16w+q) ----------
    int nloc = t >> 1;
    int hh   = t & 1;
    int n_me = w * NPW + nloc;
    int gi   = h * NST + n_me;

    float wr, wi, w32r, w32i, w64r, w64i, cmr, cmi, cm1024r, cm1024i;
    {
        float dt  = __expf(inv_dt[h]);
        float Are = -__expf(A_real[gi]);
        float Aim = A_imag[gi];
        float ar  = Are * dt;     // < 0
        float ai  = Aim * dt;

        float ea = __expf(ar);
        float sa, ca; my_sincos(ai, &sa, &ca);
        wr = ea * ca;
        wi = ea * sa;
        float er = wr - 1.0f;
        float ei = wi;

        float inv = 1.0f / fmaf(Are, Are, Aim * Aim);
        float fr = (er * Are + ei * Aim) * inv;
        float fi = (ei * Are - er * Aim) * inv;

        float br  = Bg[2 * gi], bi  = Bg[2 * gi + 1];
        float c0r = Cg[2 * gi], c0i = Cg[2 * gi + 1];
        float bcr = br * c0r - bi * c0i;
        float bci = br * c0i + bi * c0r;
        cmr = 2.0f * (bcr * fr - bci * fi);
        cmi = 2.0f * (bcr * fi + bci * fr);

        float e32 = __expf(32.0f * ar);
        float s32, c32; my_sincos(32.0f * ai, &s32, &c32);
        w32r = e32 * c32;
        w32i = e32 * s32;

        w64r = fmaf(w32r, w32r, -(w32i * w32i));
        w64i = 2.0f * w32r * w32i;
        float xr = w64r, xi = w64i;
#pragma unroll
        for (int s = 0; s < 4; s++) {              // w^1024 = (w^64)^16
            float nr = fmaf(xr, xr, -(xi * xi));
            float ni = 2.0f * xr * xi;
            xr = nr; xi = ni;
        }
        cm1024r = fmaf(cmr, xr, -(cmi * xi));
        cm1024i = fmaf(cmr, xi,  cmi * xr);
    }

    // ---------- Table generation: thread (n_me, hh) ----------
    {
        int swz  = n_me & 31;
        int swz2 = n_me & 15;

        // W1 chain: hh=0 covers w^0..w^31 into .xy, hh=1 covers w^32..w^63 into .zw
        float cr = hh ? w32r : 1.0f;
        float ci = hh ? w32i : 0.0f;
        char* w1base = (char*)(W1sh + n_me * 32) + hh * 8;
#pragma unroll
        for (int k = 0; k < 32; k++) {
            *(float2*)(w1base + (k ^ swz) * 16) = make_float2(cr, ci);
            float nr = fmaf(cr, wr, -(ci * wi));
            float ni = fmaf(cr, wi,   ci * wr);
            cr = nr; ci = ni;
        }

        // W2 chain: hh=0 covers j2=0..15 (seed Cm), hh=1 covers j2=16..31 (seed Cm*w^1024)
        float sr = hh ? cm1024r : cmr;
        float si = hh ? cm1024i : cmi;
        char* w2base = (char*)(W2sh + n_me * 16);
#pragma unroll
        for (int k = 0; k < 16; k++) {
            int j2 = hh * 16 + k;
            int p  = j2 >> 1;
            *(float2*)(w2base + (p ^ swz2) * 16 + (j2 & 1) * 8) = make_float2(sr, si);
            float nr = fmaf(sr, w64r, -(si * w64i));
            float ni = fmaf(sr, w64i,   si * w64r);
            sr = nr; si = ni;
        }
    }
    __syncthreads();

    // ---------- Main contraction ----------
    float accA[32], accB[32];
#pragma unroll
    for (int j = 0; j < 32; j++) { accA[j] = 0.0f; accB[j] = 0.0f; }

    for (int n = w * NPW; n < w * NPW + NPW; n++) {
        float4 w1 = W1sh[n * 32 + (t ^ (n & 31))];   // (w^t, w^(t+32))
        const float4* w2p = W2sh + n * 16;
        int swz2 = n & 15;
#pragma unroll
        for (int p = 0; p < 16; p++) {
            float4 w2 = w2p[p ^ swz2];               // broadcast: (W2[2p], W2[2p+1])
            int j0 = 2 * p, j1 = 2 * p + 1;
            accA[j0] = fmaf(w2.x, w1.x, accA[j0]);
            accA[j0] = fmaf(-w2.y, w1.y, accA[j0]);
            accA[j1] = fmaf(w2.z, w1.x, accA[j1]);
            accA[j1] = fmaf(-w2.w, w1.y, accA[j1]);
            accB[j0] = fmaf(w2.x, w1.z, accB[j0]);
            accB[j0] = fmaf(-w2.y, w1.w, accB[j0]);
            accB[j1] = fmaf(w2.z, w1.z, accB[j1]);
            accB[j1] = fmaf(-w2.w, w1.w, accB[j1]);
        }
    }
    __syncthreads();   // all W1/W2 reads done before overlay

    // ---------- Stage partials: red[w][a][t], a = half*32 + j2 ----------
#pragma unroll
    for (int j = 0; j < 32; j++) {
        red[(w * 64 + j) * 32 + t]      = accA[j];
        red[(w * 64 + 32 + j) * 32 + t] = accB[j];
    }
    __syncthreads();

    // ---------- Reduce 4 warps, store coalesced ----------
    float* o = out + h * LL;
    for (int e = tid; e < LL; e += 32 * NWARP) {
        int j2 = e >> 6;
        int j1 = e & 63;
        int a  = ((j1 >> 5) << 5) + j2;
        int tt = j1 & 31;
        float s = red[(0 * 64 + a) * 32 + tt] + red[(1 * 64 + a) * 32 + tt]
                + red[(2 * 64 + a) * 32 + tt] + red[(3 * 64 + a) * 32 + tt];
        o[e] = s;
    }
}

extern "C" void kernel_launch(void* const* d_in, const int* in_sizes, int n_in,
                              void* d_out, int out_size) {
    const float* A_real = (const float*)d_in[0];
    const float* A_imag = (const float*)d_in[1];
    const float* B      = (const float*)d_in[2];
    const float* C      = (const float*)d_in[3];
    const float* inv_dt = (const float*)d_in[4];
    float* out = (float*)d_out;

    s4d_all<<<HH, 32 * NWARP>>>(A_real, A_imag, B, C, inv_dt, out);
}